// round 9
// baseline (speedup 1.0000x reference)
#include <cuda_runtime.h>

// y[t, f] = x[t, f] * w[f] + b[f]
// x: [8192, 4096] f32 (134 MB), w/b: [4096] f32, out: f32 (134 MB).
//
// Conclusion after R1-R7: compulsory 268.4 MB of HBM traffic at the mixed
// read/write controller wall (~6.17 TB/s sustained on GB300). All stream
// shapes tie at ~43.5 us; cache-residency tricks regress (no persisting-L2
// carveout available). This is the simplest wall-rate kernel:
//   - one LDG.128 + one STG.128 per thread, perfectly coalesced
//   - w/b (16 KB each) L1/L2-resident via __ldg
//   - 512-thread blocks, exact-cover grid

static constexpr int TOKENS = 8192;
static constexpr int FEATURES = 4096;
static constexpr int F4_PER_ROW = FEATURES / 4;          // 1024
static constexpr int TOTAL_F4 = TOKENS * F4_PER_ROW;     // 8,388,608

__global__ void __launch_bounds__(512) one_to_one_kernel(
    const float4* __restrict__ x,
    const float4* __restrict__ w,
    const float4* __restrict__ b,
    float4* __restrict__ out)
{
    int i = blockIdx.x * blockDim.x + threadIdx.x;
    if (i >= TOTAL_F4) return;

    int c = i & (F4_PER_ROW - 1);   // column in float4 units

    float4 xv = x[i];
    float4 wv = __ldg(&w[c]);
    float4 bv = __ldg(&b[c]);

    float4 r;
    r.x = fmaf(xv.x, wv.x, bv.x);
    r.y = fmaf(xv.y, wv.y, bv.y);
    r.z = fmaf(xv.z, wv.z, bv.z);
    r.w = fmaf(xv.w, wv.w, bv.w);

    out[i] = r;
}

extern "C" void kernel_launch(void* const* d_in, const int* in_sizes, int n_in,
                              void* d_out, int out_size)
{
    const float4* x = (const float4*)d_in[0];
    const float4* w = (const float4*)d_in[1];
    const float4* b = (const float4*)d_in[2];
    float4* out = (float4*)d_out;

    const int threads = 512;
    const int blocks = (TOTAL_F4 + threads - 1) / threads;  // 16384
    one_to_one_kernel<<<blocks, threads>>>(x, w, b, out);
}

// round 10
// speedup vs baseline: 1.0368x; 1.0368x over previous
#include <cuda_runtime.h>
#include <cstdint>

// y[t, f] = x[t, f] * w[f] + b[f]
// x: [8192, 4096] f32 (134 MB), w/b: [4096] f32, out: f32 (134 MB).
//
// Final kernel (measured best, R7 config). Evidence from 8 rounds:
// compulsory 268.4 MB HBM traffic at the mixed read/write controller wall
// (~6.17 TB/s sustained on GB300). All well-occupied 256-thread stream
// shapes tie at ~43.5 us; L2 residency tricks and 512-thread blocks regress.
//   - one 256-bit ld.global.nc.v8.b32 per thread (8 contiguous floats)
//   - 2x STG.128 per thread, default cache policy
//   - w/b (16 KB each) L1/L2-resident via __ldg
//   - 256-thread blocks (highest occupancy), exact-cover grid 16384

static constexpr int TOKENS = 8192;
static constexpr int FEATURES = 4096;
static constexpr int F8_PER_ROW = FEATURES / 8;                // 512
static constexpr int TOTAL_G8 = TOKENS * F8_PER_ROW;           // 4,194,304

__device__ __forceinline__ void ldg256(const float* p, float4& lo, float4& hi) {
    uint32_t u0,u1,u2,u3,u4,u5,u6,u7;
    asm volatile("ld.global.nc.v8.b32 {%0,%1,%2,%3,%4,%5,%6,%7}, [%8];"
                 : "=r"(u0),"=r"(u1),"=r"(u2),"=r"(u3),
                   "=r"(u4),"=r"(u5),"=r"(u6),"=r"(u7)
                 : "l"(p));
    lo.x=__uint_as_float(u0); lo.y=__uint_as_float(u1);
    lo.z=__uint_as_float(u2); lo.w=__uint_as_float(u3);
    hi.x=__uint_as_float(u4); hi.y=__uint_as_float(u5);
    hi.z=__uint_as_float(u6); hi.w=__uint_as_float(u7);
}

__global__ void __launch_bounds__(256) one_to_one_kernel(
    const float* __restrict__ x,
    const float* __restrict__ w,
    const float* __restrict__ b,
    float* __restrict__ out)
{
    int i = blockIdx.x * blockDim.x + threadIdx.x;
    if (i >= TOTAL_G8) return;

    int c8 = i & (F8_PER_ROW - 1);       // column in 8-float units
    long base = (long)i * 8;             // contiguous: i spans rows implicitly

    float4 xlo, xhi;
    ldg256(x + base, xlo, xhi);

    const float4* w4 = (const float4*)(w + c8 * 8);
    const float4* b4 = (const float4*)(b + c8 * 8);
    float4 wlo = __ldg(w4), whi = __ldg(w4 + 1);
    float4 blo = __ldg(b4), bhi = __ldg(b4 + 1);

    float4 rlo, rhi;
    rlo.x = fmaf(xlo.x, wlo.x, blo.x);
    rlo.y = fmaf(xlo.y, wlo.y, blo.y);
    rlo.z = fmaf(xlo.z, wlo.z, blo.z);
    rlo.w = fmaf(xlo.w, wlo.w, blo.w);
    rhi.x = fmaf(xhi.x, whi.x, bhi.x);
    rhi.y = fmaf(xhi.y, whi.y, bhi.y);
    rhi.z = fmaf(xhi.z, whi.z, bhi.z);
    rhi.w = fmaf(xhi.w, whi.w, bhi.w);

    float4* o4 = (float4*)(out + base);
    o4[0] = rlo;
    o4[1] = rhi;
}

extern "C" void kernel_launch(void* const* d_in, const int* in_sizes, int n_in,
                              void* d_out, int out_size)
{
    const float* x = (const float*)d_in[0];
    const float* w = (const float*)d_in[1];
    const float* b = (const float*)d_in[2];
    float* out = (float*)d_out;

    const int threads = 256;
    const int blocks = (TOTAL_G8 + threads - 1) / threads;     // 16384
    one_to_one_kernel<<<blocks, threads>>>(x, w, b, out);
}